// round 17
// baseline (speedup 1.0000x reference)
#include <cuda_runtime.h>
#include <cstdint>

// ---------------------------------------------------------------------------
// TT embedding:  VOC = 100^3,  EMB = 4*4*8 = 128,  RANK = 16
//   out[tok, n1*32+n2*8+n3] = sum_{r1,r2} core0[i1,n1,r1]*core1[r1,i2,n2,r2]*core2[r2,i3,n3]
// idx = i1*10000 + i2*100 + i3; idx==0 (PAD) -> zero row.
//
// Kernel 1 : G01[i12][row*16+r2] = sum_r1 core0*core1  (10.2MB, L2-resident)
//            + fused pack of core2 into C2Q (51KB), r2 = 4c+j.  No smem.
// Kernel 2 : PERSISTENT single-wave gather: grid = 592 blocks (148 SMs x 4
//            resident) -> exactly one wave, no tail quantization.  Each warp
//            loops over ~7 tokens with a rolling depth-1 prefetch (next
//            token's idx + G row issued before the current body).  Per-token
//            body is the R10/R12-frozen minimal-wavefront layout:
//   G: 2x contiguous LDG.128 (8 wf).  C: 8 instr, one 128B line each (8 wf),
//   address-permuted so reduce round 1 needs no selects.  2-round
//   reduce-scatter, 2x contiguous STG.64.
// ---------------------------------------------------------------------------

#define VOC_LL 1000000ULL

__device__ float g_G01[10000 * 256];
__device__ float g_C2Q[100 * 128];   // [i3][j][c][n3] = core2[4c+j][i3][n3]

// ---- packed fp32x2 helpers (sm_103a) --------------------------------------
__device__ __forceinline__ unsigned long long f32x2_fma(
    unsigned long long a, unsigned long long b, unsigned long long c)
{
    unsigned long long d;
    asm("fma.rn.f32x2 %0, %1, %2, %3;" : "=l"(d) : "l"(a), "l"(b), "l"(c));
    return d;
}
__device__ __forceinline__ unsigned long long f32x2_add(
    unsigned long long a, unsigned long long b)
{
    unsigned long long d;
    asm("add.rn.f32x2 %0, %1, %2;" : "=l"(d) : "l"(a), "l"(b));
    return d;
}
__device__ __forceinline__ unsigned long long f32x2_bcast(float x)
{
    unsigned long long d;
    asm("mov.b64 %0, {%1, %1};" : "=l"(d) : "f"(x));
    return d;
}
__device__ __forceinline__ unsigned long long shfl_xor_u64(unsigned long long v, int m)
{
    unsigned int lo = (unsigned int)v, hi = (unsigned int)(v >> 32);
    lo = __shfl_xor_sync(0xffffffffu, lo, m);
    hi = __shfl_xor_sync(0xffffffffu, hi, m);
    return ((unsigned long long)hi << 32) | lo;
}

// ---------------------------------------------------------------------------
// Kernel 1: G01 precompute + fused core2 pack.  NO SMEM.  (R13 frozen)
// grid = (100, 11), block = 128.
//   y < 10 : G01 for i2 = blockIdx.x, i1 in [10y, 10y+10)
//   y == 10: pack core2 for i3 = blockIdx.x
// core0: (1,100,4,16)  elem (i1,n1,r1)    @ i1*64 + n1*16 + r1
// core1: (16,100,4,16) elem (r1,i2,n2,r2) @ r1*6400 + i2*64 + n2*16 + r2
// core2: (16,100,8)    elem (r2,i3,n3)    @ r2*800 + i3*8 + n3
// ---------------------------------------------------------------------------
__global__ void __launch_bounds__(128) tt_precompute(
    const float* __restrict__ core0,
    const float* __restrict__ core1,
    const float* __restrict__ core2)
{
    const int i2 = blockIdx.x;
    const int g  = blockIdx.y;
    const int p  = threadIdx.x;

    if (g == 10) {
        // pack: C2Q[i3*128 + p],  p = j*32 + c*8 + n3,  r2 = 4c + j
        const int i3 = i2;
        const int j  = p >> 5;
        const int c  = (p >> 3) & 3;
        const int n3 = p & 7;
        g_C2Q[i3 * 128 + p] = core2[(4 * c + j) * 800 + i3 * 8 + n3];
        return;
    }

    const int n1 = p >> 5;         // constant per warp
    const int rp = (p & 31) * 2;   // rest pair start (n2*16+r2)

    // B column straight from gmem (core1 = 400KB, L2-resident), reused 10x.
    unsigned long long b2[16];
    #pragma unroll
    for (int r1 = 0; r1 < 16; r1++)
        b2[r1] = *(const unsigned long long*)&core1[r1 * 6400 + i2 * 64 + rp];

    const float* __restrict__ a0 = core0 + (size_t)g * 640 + n1 * 16;

    #pragma unroll
    for (int q = 0; q < 10; q++) {
        unsigned long long accE = 0, accO = 0;
        #pragma unroll
        for (int r4 = 0; r4 < 4; r4++) {
            const float4 av = *(const float4*)(a0 + q * 64 + r4 * 4);
            accE = f32x2_fma(f32x2_bcast(av.x), b2[r4 * 4 + 0], accE);
            accO = f32x2_fma(f32x2_bcast(av.y), b2[r4 * 4 + 1], accO);
            accE = f32x2_fma(f32x2_bcast(av.z), b2[r4 * 4 + 2], accE);
            accO = f32x2_fma(f32x2_bcast(av.w), b2[r4 * 4 + 3], accO);
        }
        const unsigned long long acc = f32x2_add(accE, accO);
        const int i1 = g * 10 + q;
        *(unsigned long long*)&g_G01[((size_t)(i1 * 100 + i2)) * 256 + p * 2] = acc;
    }
}

// ---------------------------------------------------------------------------
// Per-token gather body (R10/R12-frozen math).  ga/gb already loaded;
// C2Q base pointers recomputed from i3 (ALU, keeps register count flat).
// ---------------------------------------------------------------------------
__device__ __forceinline__ void gather_body(
    const float4 ga, const float4 gb,
    unsigned int i3, unsigned int iv,
    int c, int b1, int k, int b2v, int n3off,
    float* __restrict__ obase)
{
    const char* base = (const char*)g_C2Q + (size_t)i3 * 512 + c * 32;
    const char* cb0  = base + 16 * b1;        // n3-half this lane KEEPS
    const char* cb1  = base + 16 * (1 - b1);  // half it will send

    const float gA[4] = { ga.x, ga.y, ga.z, ga.w };
    const float gB[4] = { gb.x, gb.y, gb.z, gb.w };

    unsigned long long aA0 = 0, aA1 = 0, aA2 = 0, aA3 = 0;
    unsigned long long aB0 = 0, aB1 = 0, aB2 = 0, aB3 = 0;
    #pragma unroll
    for (int j = 0; j < 4; j++) {
        const ulonglong2 cK = *(const ulonglong2*)(cb0 + j * 128);  // kept half
        const ulonglong2 cS = *(const ulonglong2*)(cb1 + j * 128);  // send half
        const unsigned long long ggA = f32x2_bcast(gA[j]);
        const unsigned long long ggB = f32x2_bcast(gB[j]);
        aA0 = f32x2_fma(ggA, cK.x, aA0);
        aA1 = f32x2_fma(ggA, cK.y, aA1);
        aA2 = f32x2_fma(ggA, cS.x, aA2);
        aA3 = f32x2_fma(ggA, cS.y, aA3);
        aB0 = f32x2_fma(ggB, cK.x, aB0);
        aB1 = f32x2_fma(ggB, cK.y, aB1);
        aB2 = f32x2_fma(ggB, cS.x, aB2);
        aB3 = f32x2_fma(ggB, cS.y, aB3);
    }

    // round 1 (xor 1): partner's acc2/acc3 are MY half -> no selects.
    const unsigned long long k0A = f32x2_add(aA0, shfl_xor_u64(aA2, 1));
    const unsigned long long k1A = f32x2_add(aA1, shfl_xor_u64(aA3, 1));
    const unsigned long long k0B = f32x2_add(aB0, shfl_xor_u64(aB2, 1));
    const unsigned long long k1B = f32x2_add(aB1, shfl_xor_u64(aB3, 1));

    // round 2 (xor 2): keep pair 2b1+b2, send the other pair.
    const unsigned long long kkA = b2v ? k1A : k0A;
    const unsigned long long ssA = b2v ? k0A : k1A;
    const unsigned long long kkB = b2v ? k1B : k0B;
    const unsigned long long ssB = b2v ? k0B : k1B;
    unsigned long long fA = f32x2_add(kkA, shfl_xor_u64(ssA, 2));
    unsigned long long fB = f32x2_add(kkB, shfl_xor_u64(ssB, 2));

    if (iv == 0) { fA = 0; fB = 0; }   // PAD row

    *(unsigned long long*)(obase + k * 8 + n3off)       = fA;
    *(unsigned long long*)(obase + (k + 8) * 8 + n3off) = fB;
}

// ---------------------------------------------------------------------------
// Kernel 2: persistent gather.  grid = 592 blocks (one full wave), each warp
// loops over tokens gw, gw+4736, ... with rolling depth-1 prefetch.
// lane L: k = L>>2 (rows k, k+8), c = L&3 (r2-quad [4c,4c+4)),
//         b1 = c&1 (n3-half kept), b2 = c>>1 (n3-pair kept within half).
// ---------------------------------------------------------------------------
__global__ void __launch_bounds__(256, 4) tt_gather(
    const void*  __restrict__ xraw,
    float*       __restrict__ out,
    int n_tok)
{
    const int t      = threadIdx.x;
    const int lane   = t & 31;
    const int gw     = blockIdx.x * 8 + (t >> 5);
    const int stride = gridDim.x * 8;

    // --- index dtype autodetect: one 16B broadcast load, 2 samples.
    // int32 data misread as u64 is >= VOC unless the paired hi word is 0
    // (p ~ 1e-12 for both samples); int64 data is always < VOC.
    const ulonglong2 ds = *(const ulonglong2*)xraw;
    const bool is64 = (ds.x < VOC_LL) && (ds.y < VOC_LL);

    const int k   = lane >> 2;
    const int c   = lane & 3;
    const int b1  = c & 1;
    const int b2v = (c >> 1) & 1;
    const int n3off = 4 * b1 + 2 * b2v;

    int tok = gw;
    if (tok >= n_tok) return;

    // prologue: first token's idx + G row
    long long idx0 = is64 ? ((const long long*)xraw)[tok]
                          : (long long)((const int*)xraw)[tok];
    unsigned int iv = (unsigned int)idx0;        // < 1e6
    unsigned int i3 = iv % 100u;
    {
        // rolling pipeline: prefetch next token's idx + G row, then compute
        const float4* __restrict__ Gp =
            (const float4*)(g_G01 + (size_t)(iv / 100u) * 256);
        float4 ga = Gp[lane];
        float4 gb = Gp[lane + 32];

        for (;;) {
            const int ntok = tok + stride;
            const bool more = (ntok < n_tok);

            unsigned int niv = 0, ni3 = 0;
            float4 nga = ga, ngb = gb;
            if (more) {
                const long long nidx =
                    is64 ? ((const long long*)xraw)[ntok]
                         : (long long)((const int*)xraw)[ntok];
                niv = (unsigned int)nidx;
                ni3 = niv % 100u;
                const float4* __restrict__ nGp =
                    (const float4*)(g_G01 + (size_t)(niv / 100u) * 256);
                nga = nGp[lane];              // in flight during body below
                ngb = nGp[lane + 32];
            }

            gather_body(ga, gb, i3, iv, c, b1, k, b2v, n3off,
                        out + (size_t)tok * 128);

            if (!more) break;
            tok = ntok;
            iv  = niv;
            i3  = ni3;
            ga  = nga;
            gb  = ngb;
        }
    }
}

// ---------------------------------------------------------------------------
extern "C" void kernel_launch(void* const* d_in, const int* in_sizes, int n_in,
                              void* d_out, int out_size)
{
    const void*  x     = d_in[0];
    const float* core0 = (const float*)d_in[1];
    const float* core1 = (const float*)d_in[2];
    const float* core2 = (const float*)d_in[3];
    float*       out   = (float*)d_out;

    const int n_tok = in_sizes[0];   // 32768

    tt_precompute<<<dim3(100, 11), 128>>>(core0, core1, core2);

    // one full wave: 148 SMs x 4 resident blocks
    int gblocks = 592;
    const int max_needed = (n_tok + 7) / 8;
    if (gblocks > max_needed) gblocks = max_needed;
    tt_gather<<<gblocks, 256>>>(x, out, n_tok);
}